// round 2
// baseline (speedup 1.0000x reference)
#include <cuda_runtime.h>
#include <math.h>

#define NPTS 32768
#define RS   128
#define TILE 128
#define NTHR 1024

__device__ int g_cnt[8];
__device__ int g_list[8 * NPTS];

// ---------------- smem layout (float offsets) ----------------
#define SM_XST   0
#define SM_X0T   (256 * RS)               /* 32768 */
#define SM_WS    (SM_X0T + 112 * RS)      /* 47104 */
#define SM_WD    (SM_WS + 2 * 16 * 256)   /* 55296 */
#define SM_WC2   (SM_WD + 256)            /* 55552 */
#define SM_DENS  (SM_WC2 + 388)           /* 55940 */
#define SM_GIDX  (SM_DENS + 128)          /* 56068 */
#define SM_TOTALF (SM_GIDX + 128)
#define SMEM_BYTES (SM_TOTALF * 4)

// ---------------- packed f32x2 helpers ----------------
__device__ __forceinline__ unsigned long long dup2(float v) {
    unsigned long long r;
    asm("mov.b64 %0, {%1, %1};" : "=l"(r) : "f"(v));
    return r;
}
__device__ __forceinline__ void fma2(unsigned long long& d, unsigned long long a, unsigned long long b) {
    asm("fma.rn.f32x2 %0, %1, %2, %0;" : "+l"(d) : "l"(a), "l"(b));
}
__device__ __forceinline__ void unpack2(unsigned long long v, float& lo, float& hi) {
    asm("mov.b64 {%0, %1}, %2;" : "=f"(lo), "=f"(hi) : "l"(v));
}

// ---------------- cp.async helpers ----------------
__device__ __forceinline__ void cpasync16(unsigned saddr, const void* g, int srcsz) {
    asm volatile("cp.async.cg.shared.global [%0], [%1], 16, %2;"
                 :: "r"(saddr), "l"(g), "r"(srcsz));
}
__device__ __forceinline__ void cp_commit() { asm volatile("cp.async.commit_group;"); }
template <int n> __device__ __forceinline__ void cp_wait() {
    asm volatile("cp.async.wait_group %0;" :: "n"(n));
}

// Stage 16 rows x NCOL cols of W (rows [k0,k0+16), skip past K) into smem.
template <int NCOL>
__device__ __forceinline__ void stage16(float* ws, const float* __restrict__ Wg,
                                        int k0, int K, int tid) {
    if (NCOL == 256) {
        int row = tid >> 6, col = (tid & 63) * 4;
        int gr = k0 + row;
        cpasync16((unsigned)__cvta_generic_to_shared(ws + row * 256 + col),
                  Wg + (size_t)(gr < K ? gr : 0) * 256 + col, gr < K ? 16 : 0);
    } else {
        if (tid < 512) {
            int row = tid >> 5, col = (tid & 31) * 4;
            int gr = k0 + row;
            cpasync16((unsigned)__cvta_generic_to_shared(ws + row * 128 + col),
                      Wg + (size_t)(gr < K ? gr : 0) * 128 + col, gr < K ? 16 : 0);
        }
    }
}

// One dense layer over a 128-point tile.
// Mapping: lane = point-within-group, warp -> (col-block cb = w>>2, point-group pg = w&3).
// Each thread: 1 point x 32 cols (16 packed f32x2 accumulators).
template <int NCOL>
__device__ __noinline__ void dense_layer(
    float* sm,
    const float* s1, int K1, const float* W1,
    const float* s2, int K2, const float* W2,
    const float* __restrict__ bias, int act, float* dstT)
{
    const int tid = threadIdx.x;
    const int w = tid >> 5, l = tid & 31;
    const int cb = w >> 2;            // col block (0..7)
    const int p  = (w & 3) * 32 + l;  // point (0..127)
    const bool active = (cb < NCOL / 32);
    float* Ws = sm + SM_WS;

    unsigned long long acc[16];
    if (active) {
        const ulonglong2* bp = (const ulonglong2*)(bias + cb * 32);
#pragma unroll
        for (int j = 0; j < 8; j++) {
            ulonglong2 u = bp[j];
            acc[2 * j] = u.x; acc[2 * j + 1] = u.y;
        }
    }

#pragma unroll 1
    for (int s = 0; s < 2; s++) {
        const float* src = s ? s2 : s1;
        int K           = s ? K2 : K1;
        const float* Wg = s ? W2 : W1;
        if (K == 0) continue;
        int nch = (K + 15) >> 4;

        if (s) __syncthreads();   // guard buffer reuse across segments
        stage16<NCOL>(Ws, Wg, 0, K, tid);
        cp_commit();

#pragma unroll 1
        for (int c = 0; c < nch; c++) {
            cp_wait<0>();
            __syncthreads();
            // Stage next chunk AFTER the barrier: all reads of the target
            // buffer (done in compute(c-1)) are ordered before this write.
            if (c + 1 < nch) {
                stage16<NCOL>(Ws + ((c + 1) & 1) * 4096, Wg, (c + 1) * 16, K, tid);
                cp_commit();
            }
            if (active) {
                const float* Wb = Ws + (c & 1) * 4096;
                int kend = K - c * 16; if (kend > 16) kend = 16;
                const float* xp = src + (size_t)(c * 16) * RS + p;
#pragma unroll 4
                for (int kk = 0; kk < kend; kk++) {
                    unsigned long long xd = dup2(xp[kk * RS]);
                    const ulonglong2* wp = (const ulonglong2*)(Wb + kk * NCOL + cb * 32);
#pragma unroll
                    for (int j = 0; j < 8; j++) {
                        ulonglong2 u = wp[j];
                        fma2(acc[2 * j],     xd, u.x);
                        fma2(acc[2 * j + 1], xd, u.y);
                    }
                }
            }
        }
    }

    __syncthreads();   // all reads of src done before in-place writeback
    if (active) {
#pragma unroll
        for (int j = 0; j < 16; j++) {
            float lo, hi; unpack2(acc[j], lo, hi);
            if (act) { lo = fmaxf(lo, 0.f); hi = fmaxf(hi, 0.f); }
            dstT[(cb * 32 + 2 * j) * RS + p]     = lo;
            dstT[(cb * 32 + 2 * j + 1) * RS + p] = hi;
        }
    }
    __syncthreads();
}

// ---------------- pass 0/1: zero + routing ----------------
__global__ void k_zero() { if (threadIdx.x < 8) g_cnt[threadIdx.x] = 0; }

__global__ void k_route(const float* __restrict__ pts, float* __restrict__ out) {
    int i = blockIdx.x * blockDim.x + threadIdx.x;
    if (i >= NPTS) return;
    float x = pts[3 * i], y = pts[3 * i + 1], z = pts[3 * i + 2];
    bool fg = (x >= -80.f) && (x <= 80.f) && (y >= -80.f) && (y <= 80.f)
           && (z >= -4.f) && (z <= 44.f);
    if (!fg) {
        out[i] = 0.f;
        out[NPTS + 3 * i] = 0.f; out[NPTS + 3 * i + 1] = 0.f; out[NPTS + 3 * i + 2] = 0.f;
        return;
    }
    int jx = (x > 0.f) ? 1 : 0;
    int iy = (y > 50.f) ? 3 : (y > 0.f) ? 2 : (y > -50.f) ? 1 : 0;
    int e = iy * 2 + jx;
    int pos = atomicAdd(&g_cnt[e], 1);
    g_list[e * NPTS + pos] = i;
}

// ---------------- pass 2: full MLP per (expert, 128-pt tile) ----------------
__global__ void __launch_bounds__(NTHR, 1) k_mlp(
    const float* __restrict__ pts, const float* __restrict__ vds,
    const int* __restrict__ aidx, const float* __restrict__ app,
    const float* __restrict__ W0, const float* __restrict__ b0,
    const float* __restrict__ Wpre, const float* __restrict__ bpre,
    const float* __restrict__ Wskip, const float* __restrict__ bskip,
    const float* __restrict__ Wpost, const float* __restrict__ bpost,
    const float* __restrict__ Wd, const float* __restrict__ bd,
    const float* __restrict__ Wf, const float* __restrict__ bf,
    const float* __restrict__ Wc1, const float* __restrict__ bc1,
    const float* __restrict__ Wc2, const float* __restrict__ bc2,
    float* __restrict__ out)
{
    const int e = blockIdx.y;
    const int cnt = g_cnt[e];
    const int base = blockIdx.x * TILE;
    if (base >= cnt) return;
    const int npts = min(TILE, cnt - base);

    extern __shared__ float sm[];
    float* xsT  = sm + SM_XST;
    float* x0T  = sm + SM_X0T;
    float* WdS  = sm + SM_WD;
    float* Wc2S = sm + SM_WC2;
    float* dens = sm + SM_DENS;
    int*   gidx = (int*)(sm + SM_GIDX);

    const int tid = threadIdx.x;

    // ---- setup: posenc (t<512, 4 threads/pt) / appearance (t>=512) ----
    if (tid < 512) {
        int pt = tid >> 2, q = tid & 3;
        if (pt < npts) {
            int g = g_list[e * NPTS + base + pt];
            float px = pts[3 * g], py = pts[3 * g + 1], pz = pts[3 * g + 2];
            if (q == 0) {
                gidx[pt] = g;
                x0T[0 * RS + pt] = px; x0T[1 * RS + pt] = py; x0T[2 * RS + pt] = pz;
            }
#pragma unroll 1
            for (int i = q; i < 10; i += 4) {
                float f = (float)exp2((double)i * (10.0 / 9.0));  // match numpy f64->f32
                int r = 3 + 6 * i;
                double ax = (double)(f * px), ay = (double)(f * py), az = (double)(f * pz);
                x0T[(r + 0) * RS + pt] = (float)sin(ax);
                x0T[(r + 1) * RS + pt] = (float)sin(ay);
                x0T[(r + 2) * RS + pt] = (float)sin(az);
                x0T[(r + 3) * RS + pt] = (float)cos(ax);
                x0T[(r + 4) * RS + pt] = (float)cos(ay);
                x0T[(r + 5) * RS + pt] = (float)cos(az);
            }
        } else {
            if (q == 0) gidx[pt] = 0;
#pragma unroll 1
            for (int r = q; r < 63; r += 4) x0T[r * RS + pt] = 0.f;
        }
    } else {
        int s2 = tid - 512;
        int pt = s2 >> 2, q = s2 & 3;
        if (pt < npts) {
            int g = g_list[e * NPTS + base + pt];
            int ai = aidx[g];
            const float* a = app + ((size_t)e * 1000 + ai) * 48;
#pragma unroll 1
            for (int j = q; j < 48; j += 4) x0T[(63 + j) * RS + pt] = a[j];
        } else {
#pragma unroll 1
            for (int j = q; j < 48; j += 4) x0T[(63 + j) * RS + pt] = 0.f;
        }
    }
    // small weights
    if (tid < 256)      WdS[tid] = Wd[e * 256 + tid];
    else if (tid < 640) Wc2S[tid - 256] = Wc2[e * 384 + (tid - 256)];
    else if (tid < 643) Wc2S[384 + (tid - 640)] = bc2[e * 3 + (tid - 640)];
    __syncthreads();

    // ---- trunk ----
    dense_layer<256>(sm, x0T, 111, W0 + (size_t)e * 111 * 256,
                     nullptr, 0, nullptr, b0 + e * 256, 1, xsT);
#pragma unroll 1
    for (int i = 0; i < 3; i++)
        dense_layer<256>(sm, xsT, 256, Wpre + ((size_t)e * 3 + i) * 65536,
                         nullptr, 0, nullptr, bpre + (e * 3 + i) * 256, 1, xsT);
    dense_layer<256>(sm, xsT, 256, Wskip + (size_t)e * 367 * 256,
                     x0T, 111, Wskip + (size_t)e * 367 * 256 + 256 * 256,
                     bskip + e * 256, 1, xsT);

    // ---- direnc: x0 is dead after the skip layer; reuse its smem for deT ----
    float* deT = x0T;
    if (tid < 512) {
        int pt = tid >> 2, q = tid & 3;
        if (pt < npts) {
            int g = gidx[pt];
            float vx = vds[3 * g], vy = vds[3 * g + 1], vz = vds[3 * g + 2];
            if (q == 0) {
                deT[0 * RS + pt] = vx; deT[1 * RS + pt] = vy; deT[2 * RS + pt] = vz;
            }
            {
                int i = q;  // exactly one frequency per thread (4 freqs)
                float f = (float)exp2((double)i * (4.0 / 3.0));
                int r = 3 + 6 * i;
                double ax = (double)(f * vx), ay = (double)(f * vy), az = (double)(f * vz);
                deT[(r + 0) * RS + pt] = (float)sin(ax);
                deT[(r + 1) * RS + pt] = (float)sin(ay);
                deT[(r + 2) * RS + pt] = (float)sin(az);
                deT[(r + 3) * RS + pt] = (float)cos(ax);
                deT[(r + 4) * RS + pt] = (float)cos(ay);
                deT[(r + 5) * RS + pt] = (float)cos(az);
            }
        } else {
#pragma unroll 1
            for (int r = q; r < 27; r += 4) deT[r * RS + pt] = 0.f;
        }
    }
    // (no barrier needed here: many barriers occur before deT is consumed)

#pragma unroll 1
    for (int i = 0; i < 3; i++)
        dense_layer<256>(sm, xsT, 256, Wpost + ((size_t)e * 3 + i) * 65536,
                         nullptr, 0, nullptr, bpost + (e * 3 + i) * 256, 1, xsT);

    // ---- density head: 8 threads per point ----
    {
        int p = tid >> 3, kb = tid & 7;
        float s = 0.f;
#pragma unroll 8
        for (int j = 0; j < 32; j++) {
            int k = kb * 32 + j;
            s += xsT[k * RS + p] * WdS[k];
        }
        s += __shfl_xor_sync(0xffffffffu, s, 4);
        s += __shfl_xor_sync(0xffffffffu, s, 2);
        s += __shfl_xor_sync(0xffffffffu, s, 1);
        if ((tid & 7) == 0) dens[p] = fmaxf(s + bd[e], 0.f);
    }
    __syncthreads();

    // ---- feature (no relu) ----
    dense_layer<256>(sm, xsT, 256, Wf + (size_t)e * 65536,
                     nullptr, 0, nullptr, bf + e * 256, 0, xsT);

    // ---- color hidden (relu) -> xsT rows 0..127 ----
    dense_layer<128>(sm, xsT, 256, Wc1 + (size_t)e * 283 * 128,
                     deT, 27, Wc1 + (size_t)e * 283 * 128 + 256 * 128,
                     bc1 + e * 128, 1, xsT);

    // ---- color output + final writes ----
    if (tid < 384) {
        int pt = tid / 3, cc = tid - 3 * pt;
        float s = Wc2S[384 + cc];
#pragma unroll 8
        for (int k = 0; k < 128; k++) s += xsT[k * RS + pt] * Wc2S[k * 3 + cc];
        if (pt < npts) out[NPTS + 3 * gidx[pt] + cc] = 1.f / (1.f + expf(-s));
    }
    if (tid < 128 && tid < npts) out[gidx[tid]] = dens[tid];
}

// ---------------- launch ----------------
extern "C" void kernel_launch(void* const* d_in, const int* in_sizes, int n_in,
                              void* d_out, int out_size) {
    const float* pts   = (const float*)d_in[0];
    const float* vds   = (const float*)d_in[1];
    const int*   aidx  = (const int*)d_in[2];
    const float* app   = (const float*)d_in[3];
    const float* W0    = (const float*)d_in[4];
    const float* b0    = (const float*)d_in[5];
    const float* Wpre  = (const float*)d_in[6];
    const float* bpre  = (const float*)d_in[7];
    const float* Wskip = (const float*)d_in[8];
    const float* bskip = (const float*)d_in[9];
    const float* Wpost = (const float*)d_in[10];
    const float* bpost = (const float*)d_in[11];
    const float* Wd    = (const float*)d_in[12];
    const float* bd    = (const float*)d_in[13];
    const float* Wf    = (const float*)d_in[14];
    const float* bf    = (const float*)d_in[15];
    const float* Wc1   = (const float*)d_in[16];
    const float* bc1   = (const float*)d_in[17];
    const float* Wc2   = (const float*)d_in[18];
    const float* bc2   = (const float*)d_in[19];
    float* out = (float*)d_out;

    static bool attr_done = false;
    if (!attr_done) {
        cudaFuncSetAttribute(k_mlp, cudaFuncAttributeMaxDynamicSharedMemorySize, SMEM_BYTES);
        attr_done = true;
    }

    k_zero<<<1, 32>>>();
    k_route<<<NPTS / 256, 256>>>(pts, out);
    dim3 grid(64, 8);   // 64 tiles/expert capacity (>= ~21 expected); empties exit fast
    k_mlp<<<grid, NTHR, SMEM_BYTES>>>(pts, vds, aidx, app, W0, b0, Wpre, bpre,
                                      Wskip, bskip, Wpost, bpost, Wd, bd, Wf, bf,
                                      Wc1, bc1, Wc2, bc2, out);
}

// round 4
// speedup vs baseline: 1.5186x; 1.5186x over previous
#include <cuda_runtime.h>
#include <math.h>

#define NPTS 32768
#define RS   128
#define TILE 128
#define NTHR 512
#define NCTA 148

__device__ int g_cnt[8];
__device__ int g_list[8 * NPTS];

// ---------------- smem layout (float offsets) ----------------
#define SM_XST   0
#define SM_X0T   (256 * RS)               /* 32768 */
#define SM_WS    (SM_X0T + 112 * RS)      /* 47104 */
#define SM_WD    (SM_WS + 2 * 16 * 256)   /* 55296 */
#define SM_WC2   (SM_WD + 256)            /* 55552 */
#define SM_DENS  (SM_WC2 + 388)           /* 55940 */
#define SM_GIDX  (SM_DENS + 128)          /* 56068 */
#define SM_TOTALF (SM_GIDX + 128)
#define SMEM_BYTES (SM_TOTALF * 4)

// ---------------- packed f32x2 helpers ----------------
__device__ __forceinline__ unsigned long long dup2(float v) {
    unsigned long long r;
    asm("mov.b64 %0, {%1, %1};" : "=l"(r) : "f"(v));
    return r;
}
__device__ __forceinline__ void fma2(unsigned long long& d, unsigned long long a, unsigned long long b) {
    asm("fma.rn.f32x2 %0, %1, %2, %0;" : "+l"(d) : "l"(a), "l"(b));
}
__device__ __forceinline__ void unpack2(unsigned long long v, float& lo, float& hi) {
    asm("mov.b64 {%0, %1}, %2;" : "=f"(lo), "=f"(hi) : "l"(v));
}

// ---------------- cp.async helpers ----------------
__device__ __forceinline__ void cpasync16(unsigned saddr, const void* g, int srcsz) {
    asm volatile("cp.async.cg.shared.global [%0], [%1], 16, %2;"
                 :: "r"(saddr), "l"(g), "r"(srcsz));
}
__device__ __forceinline__ void cp_commit() { asm volatile("cp.async.commit_group;"); }
template <int n> __device__ __forceinline__ void cp_wait() {
    asm volatile("cp.async.wait_group %0;" :: "n"(n));
}

// Stage 16 rows x NCOL cols of W (rows [k0,k0+16), zero-size past K) into smem.
template <int NCOL>
__device__ __forceinline__ void stage16(float* ws, const float* __restrict__ Wg,
                                        int k0, int K, int tid) {
    if (NCOL == 256) {
        int row = tid >> 5, colb = (tid & 31) * 4;
        int gr = k0 + row;
        int sz = (gr < K) ? 16 : 0;
        const float* g = Wg + (size_t)(gr < K ? gr : 0) * 256;
        unsigned sa = (unsigned)__cvta_generic_to_shared(ws + row * 256);
        cpasync16(sa + colb * 4, g + colb, sz);
        cpasync16(sa + (colb + 128) * 4, g + colb + 128, sz);
    } else {
        int row = tid >> 5, colb = (tid & 31) * 4;
        int gr = k0 + row;
        int sz = (gr < K) ? 16 : 0;
        cpasync16((unsigned)__cvta_generic_to_shared(ws + row * 128 + colb),
                  Wg + (size_t)(gr < K ? gr : 0) * 128 + colb, sz);
    }
}

// One dense layer over a 128-point tile, 512 threads.
// Warp w (0..15): cb = w&7 (32-col block), pg = w>>3 (64-pt group).
// Lane l: cols c0 = cb*32 + (l&3)*8 ; pts p0 = pg*64 + (l>>2)*8.
// All LDS.128 are 128B-dense across the warp (no broadcast waste).
template <int NCOL>
__device__ __noinline__ void dense_layer(
    float* sm,
    const float* s1, int K1, const float* W1,
    const float* s2, int K2, const float* W2,
    const float* __restrict__ bias, int act, float* dstT)
{
    const int tid = threadIdx.x;
    const int w = tid >> 5, l = tid & 31;
    const int cb = w & 7;
    const int pg = w >> 3;
    const int c0 = cb * 32 + (l & 3) * 8;
    const int p0 = pg * 64 + (l >> 2) * 8;
    const bool active = (cb < NCOL / 32);
    float* Ws = sm + SM_WS;

    unsigned long long acc[8][4];   // [col j][pt-pair i]
    if (active) {
#pragma unroll
        for (int j = 0; j < 8; j++) {
            unsigned long long b = dup2(bias[c0 + j]);
            acc[j][0] = b; acc[j][1] = b; acc[j][2] = b; acc[j][3] = b;
        }
    }

#pragma unroll 1
    for (int s = 0; s < 2; s++) {
        const float* src = s ? s2 : s1;
        int K           = s ? K2 : K1;
        const float* Wg = s ? W2 : W1;
        if (K == 0) continue;
        int nch = (K + 15) >> 4;

        if (s) __syncthreads();   // guard buffer reuse across segments
        stage16<NCOL>(Ws, Wg, 0, K, tid);
        cp_commit();

#pragma unroll 1
        for (int c = 0; c < nch; c++) {
            cp_wait<0>();
            __syncthreads();
            // Stage next chunk AFTER the barrier: all reads of the target
            // buffer (compute(c-1)) are ordered before this write.
            if (c + 1 < nch) {
                stage16<NCOL>(Ws + ((c + 1) & 1) * 4096, Wg, (c + 1) * 16, K, tid);
                cp_commit();
            }
            if (active) {
                const float* Wb = Ws + (c & 1) * 4096;
                int kend = K - c * 16; if (kend > 16) kend = 16;
                const float* xp = src + (size_t)(c * 16) * RS + p0;
                const float* wp = Wb + c0;
#pragma unroll 2
                for (int kk = 0; kk < kend; kk++) {
                    ulonglong2 xa = *(const ulonglong2*)(xp);
                    ulonglong2 xb = *(const ulonglong2*)(xp + 4);
                    xp += RS;
                    float4 w0 = *(const float4*)(wp);
                    float4 w1 = *(const float4*)(wp + 4);
                    wp += NCOL;
                    unsigned long long wd;
                    wd = dup2(w0.x);
                    fma2(acc[0][0], xa.x, wd); fma2(acc[0][1], xa.y, wd);
                    fma2(acc[0][2], xb.x, wd); fma2(acc[0][3], xb.y, wd);
                    wd = dup2(w0.y);
                    fma2(acc[1][0], xa.x, wd); fma2(acc[1][1], xa.y, wd);
                    fma2(acc[1][2], xb.x, wd); fma2(acc[1][3], xb.y, wd);
                    wd = dup2(w0.z);
                    fma2(acc[2][0], xa.x, wd); fma2(acc[2][1], xa.y, wd);
                    fma2(acc[2][2], xb.x, wd); fma2(acc[2][3], xb.y, wd);
                    wd = dup2(w0.w);
                    fma2(acc[3][0], xa.x, wd); fma2(acc[3][1], xa.y, wd);
                    fma2(acc[3][2], xb.x, wd); fma2(acc[3][3], xb.y, wd);
                    wd = dup2(w1.x);
                    fma2(acc[4][0], xa.x, wd); fma2(acc[4][1], xa.y, wd);
                    fma2(acc[4][2], xb.x, wd); fma2(acc[4][3], xb.y, wd);
                    wd = dup2(w1.y);
                    fma2(acc[5][0], xa.x, wd); fma2(acc[5][1], xa.y, wd);
                    fma2(acc[5][2], xb.x, wd); fma2(acc[5][3], xb.y, wd);
                    wd = dup2(w1.z);
                    fma2(acc[6][0], xa.x, wd); fma2(acc[6][1], xa.y, wd);
                    fma2(acc[6][2], xb.x, wd); fma2(acc[6][3], xb.y, wd);
                    wd = dup2(w1.w);
                    fma2(acc[7][0], xa.x, wd); fma2(acc[7][1], xa.y, wd);
                    fma2(acc[7][2], xb.x, wd); fma2(acc[7][3], xb.y, wd);
                }
            }
        }
    }

    __syncthreads();   // all reads of src done before in-place writeback
    if (active) {
#pragma unroll
        for (int j = 0; j < 8; j++) {
            float v[8];
            unpack2(acc[j][0], v[0], v[1]);
            unpack2(acc[j][1], v[2], v[3]);
            unpack2(acc[j][2], v[4], v[5]);
            unpack2(acc[j][3], v[6], v[7]);
            if (act) {
#pragma unroll
                for (int q = 0; q < 8; q++) v[q] = fmaxf(v[q], 0.f);
            }
            float* d = dstT + (size_t)(c0 + j) * RS + p0;
            *(float4*)(d)     = make_float4(v[0], v[1], v[2], v[3]);
            *(float4*)(d + 4) = make_float4(v[4], v[5], v[6], v[7]);
        }
    }
    __syncthreads();
}

// ---------------- pass 0/1: zero + routing ----------------
__global__ void k_zero() { if (threadIdx.x < 8) g_cnt[threadIdx.x] = 0; }

__global__ void k_route(const float* __restrict__ pts, float* __restrict__ out) {
    int i = blockIdx.x * blockDim.x + threadIdx.x;
    if (i >= NPTS) return;
    float x = pts[3 * i], y = pts[3 * i + 1], z = pts[3 * i + 2];
    bool fg = (x >= -80.f) && (x <= 80.f) && (y >= -80.f) && (y <= 80.f)
           && (z >= -4.f) && (z <= 44.f);
    if (!fg) {
        out[i] = 0.f;
        out[NPTS + 3 * i] = 0.f; out[NPTS + 3 * i + 1] = 0.f; out[NPTS + 3 * i + 2] = 0.f;
        return;
    }
    int jx = (x > 0.f) ? 1 : 0;
    int iy = (y > 50.f) ? 3 : (y > 0.f) ? 2 : (y > -50.f) ? 1 : 0;
    int e = iy * 2 + jx;
    int pos = atomicAdd(&g_cnt[e], 1);
    g_list[e * NPTS + pos] = i;
}

// ---------------- pass 2: persistent CTAs over all (expert, tile) ----------------
__global__ void __launch_bounds__(NTHR, 1) k_mlp(
    const float* __restrict__ pts, const float* __restrict__ vds,
    const int* __restrict__ aidx, const float* __restrict__ app,
    const float* __restrict__ W0, const float* __restrict__ b0,
    const float* __restrict__ Wpre, const float* __restrict__ bpre,
    const float* __restrict__ Wskip, const float* __restrict__ bskip,
    const float* __restrict__ Wpost, const float* __restrict__ bpost,
    const float* __restrict__ Wd, const float* __restrict__ bd,
    const float* __restrict__ Wf, const float* __restrict__ bf,
    const float* __restrict__ Wc1, const float* __restrict__ bc1,
    const float* __restrict__ Wc2, const float* __restrict__ bc2,
    float* __restrict__ out)
{
    extern __shared__ float sm[];
    float* xsT  = sm + SM_XST;
    float* x0T  = sm + SM_X0T;
    float* WdS  = sm + SM_WD;
    float* Wc2S = sm + SM_WC2;
    float* dens = sm + SM_DENS;
    int*   gidx = (int*)(sm + SM_GIDX);

    const int tid = threadIdx.x;

    // Per-expert tile prefix (identical in every thread/CTA).
    int cnt8[8], tb[8], tot = 0;
#pragma unroll
    for (int e8 = 0; e8 < 8; e8++) {
        cnt8[e8] = g_cnt[e8];
        tb[e8] = tot;
        tot += (cnt8[e8] + TILE - 1) / TILE;
    }

#pragma unroll 1
    for (int tile = blockIdx.x; tile < tot; tile += gridDim.x) {
        int e = 0;
#pragma unroll
        for (int e8 = 1; e8 < 8; e8++) if (tile >= tb[e8]) e = e8;
        const int cnt  = cnt8[e];
        const int base = (tile - tb[e]) * TILE;
        const int npts = min(TILE, cnt - base);

        // ---- setup: posenc (4 threads/pt) ----
        {
            int pt = tid >> 2, q = tid & 3;
            if (pt < npts) {
                int g = g_list[e * NPTS + base + pt];
                float px = pts[3 * g], py = pts[3 * g + 1], pz = pts[3 * g + 2];
                if (q == 0) {
                    gidx[pt] = g;
                    x0T[0 * RS + pt] = px; x0T[1 * RS + pt] = py; x0T[2 * RS + pt] = pz;
                }
#pragma unroll 1
                for (int i = q; i < 10; i += 4) {
                    float f = (float)exp2((double)i * (10.0 / 9.0));  // match numpy f64->f32
                    int r = 3 + 6 * i;
                    double ax = (double)(f * px), ay = (double)(f * py), az = (double)(f * pz);
                    x0T[(r + 0) * RS + pt] = (float)sin(ax);
                    x0T[(r + 1) * RS + pt] = (float)sin(ay);
                    x0T[(r + 2) * RS + pt] = (float)sin(az);
                    x0T[(r + 3) * RS + pt] = (float)cos(ax);
                    x0T[(r + 4) * RS + pt] = (float)cos(ay);
                    x0T[(r + 5) * RS + pt] = (float)cos(az);
                }
            } else {
                if (q == 0) gidx[pt] = 0;
#pragma unroll 1
                for (int r = q; r < 63; r += 4) x0T[r * RS + pt] = 0.f;
            }
        }
        // ---- appearance (4 threads/pt) ----
        {
            int pt = tid >> 2, q = tid & 3;
            if (pt < npts) {
                int g = g_list[e * NPTS + base + pt];
                int ai = aidx[g];
                const float* a = app + ((size_t)e * 1000 + ai) * 48;
#pragma unroll 1
                for (int j = q; j < 48; j += 4) x0T[(63 + j) * RS + pt] = a[j];
            } else {
#pragma unroll 1
                for (int j = q; j < 48; j += 4) x0T[(63 + j) * RS + pt] = 0.f;
            }
        }
        // small weights
        if (tid < 256)      WdS[tid] = Wd[e * 256 + tid];
        if (tid >= 256 && tid < 512) {
            int t = tid - 256;
            Wc2S[t] = Wc2[e * 384 + t];
            if (t < 128) Wc2S[256 + t] = Wc2[e * 384 + 256 + t];
            if (t < 3)   Wc2S[384 + t] = bc2[e * 3 + t];
        }
        __syncthreads();

        // ---- trunk ----
        dense_layer<256>(sm, x0T, 111, W0 + (size_t)e * 111 * 256,
                         nullptr, 0, nullptr, b0 + e * 256, 1, xsT);
#pragma unroll 1
        for (int i = 0; i < 3; i++)
            dense_layer<256>(sm, xsT, 256, Wpre + ((size_t)e * 3 + i) * 65536,
                             nullptr, 0, nullptr, bpre + (e * 3 + i) * 256, 1, xsT);
        dense_layer<256>(sm, xsT, 256, Wskip + (size_t)e * 367 * 256,
                         x0T, 111, Wskip + (size_t)e * 367 * 256 + 256 * 256,
                         bskip + e * 256, 1, xsT);

        // ---- direnc: x0 dead after skip layer; reuse its smem for deT ----
        float* deT = x0T;
        {
            int pt = tid >> 2, q = tid & 3;
            if (pt < npts) {
                int g = gidx[pt];
                float vx = vds[3 * g], vy = vds[3 * g + 1], vz = vds[3 * g + 2];
                if (q == 0) {
                    deT[0 * RS + pt] = vx; deT[1 * RS + pt] = vy; deT[2 * RS + pt] = vz;
                }
                {
                    int i = q;
                    float f = (float)exp2((double)i * (4.0 / 3.0));
                    int r = 3 + 6 * i;
                    double ax = (double)(f * vx), ay = (double)(f * vy), az = (double)(f * vz);
                    deT[(r + 0) * RS + pt] = (float)sin(ax);
                    deT[(r + 1) * RS + pt] = (float)sin(ay);
                    deT[(r + 2) * RS + pt] = (float)sin(az);
                    deT[(r + 3) * RS + pt] = (float)cos(ax);
                    deT[(r + 4) * RS + pt] = (float)cos(ay);
                    deT[(r + 5) * RS + pt] = (float)cos(az);
                }
            } else {
#pragma unroll 1
                for (int r = q; r < 27; r += 4) deT[r * RS + pt] = 0.f;
            }
        }
        // (no barrier needed: many barriers occur before deT is consumed)

#pragma unroll 1
        for (int i = 0; i < 3; i++)
            dense_layer<256>(sm, xsT, 256, Wpost + ((size_t)e * 3 + i) * 65536,
                             nullptr, 0, nullptr, bpost + (e * 3 + i) * 256, 1, xsT);

        // ---- density head: 4 threads per point ----
        {
            int p = tid >> 2, kb = tid & 3;
            float s = 0.f;
#pragma unroll 8
            for (int j = 0; j < 64; j++) {
                int k = kb * 64 + j;
                s += xsT[k * RS + p] * WdS[k];
            }
            s += __shfl_xor_sync(0xffffffffu, s, 2);
            s += __shfl_xor_sync(0xffffffffu, s, 1);
            if (kb == 0) dens[p] = fmaxf(s + bd[e], 0.f);
        }
        __syncthreads();

        // ---- feature (no relu) ----
        dense_layer<256>(sm, xsT, 256, Wf + (size_t)e * 65536,
                         nullptr, 0, nullptr, bf + e * 256, 0, xsT);

        // ---- color hidden (relu) -> xsT rows 0..127 ----
        dense_layer<128>(sm, xsT, 256, Wc1 + (size_t)e * 283 * 128,
                         deT, 27, Wc1 + (size_t)e * 283 * 128 + 256 * 128,
                         bc1 + e * 128, 1, xsT);

        // ---- color output + final writes ----
        if (tid < 384) {
            int pt = tid / 3, cc = tid - 3 * pt;
            float s = Wc2S[384 + cc];
#pragma unroll 8
            for (int k = 0; k < 128; k++) s += xsT[k * RS + pt] * Wc2S[k * 3 + cc];
            if (pt < npts) out[NPTS + 3 * gidx[pt] + cc] = 1.f / (1.f + expf(-s));
        }
        if (tid < 128 && tid < npts) out[gidx[tid]] = dens[tid];

        __syncthreads();   // smem (xsT/x0T/gidx/dens/Wc2S) reused next tile
    }
}

// ---------------- launch ----------------
extern "C" void kernel_launch(void* const* d_in, const int* in_sizes, int n_in,
                              void* d_out, int out_size) {
    const float* pts   = (const float*)d_in[0];
    const float* vds   = (const float*)d_in[1];
    const int*   aidx  = (const int*)d_in[2];
    const float* app   = (const float*)d_in[3];
    const float* W0    = (const float*)d_in[4];
    const float* b0    = (const float*)d_in[5];
    const float* Wpre  = (const float*)d_in[6];
    const float* bpre  = (const float*)d_in[7];
    const float* Wskip = (const float*)d_in[8];
    const float* bskip = (const float*)d_in[9];
    const float* Wpost = (const float*)d_in[10];
    const float* bpost = (const float*)d_in[11];
    const float* Wd    = (const float*)d_in[12];
    const float* bd    = (const float*)d_in[13];
    const float* Wf    = (const float*)d_in[14];
    const float* bf    = (const float*)d_in[15];
    const float* Wc1   = (const float*)d_in[16];
    const float* bc1   = (const float*)d_in[17];
    const float* Wc2   = (const float*)d_in[18];
    const float* bc2   = (const float*)d_in[19];
    float* out = (float*)d_out;

    static bool attr_done = false;
    if (!attr_done) {
        cudaFuncSetAttribute(k_mlp, cudaFuncAttributeMaxDynamicSharedMemorySize, SMEM_BYTES);
        attr_done = true;
    }

    k_zero<<<1, 32>>>();
    k_route<<<NPTS / 256, 256>>>(pts, out);
    k_mlp<<<NCTA, NTHR, SMEM_BYTES>>>(pts, vds, aidx, app, W0, b0, Wpre, bpre,
                                      Wskip, bskip, Wpost, bpost, Wd, bd, Wf, bf,
                                      Wc1, bc1, Wc2, bc2, out);
}